// round 17
// baseline (speedup 1.0000x reference)
#include <cuda_runtime.h>
#include <cuda_fp16.h>
#include <stdint.h>

#define D 768
#define H 64
#define E 7
#define BMAX 32768
#define NHB 64
#define CPE 19            // CTAs per expert (persistent stride over 256-row tiles)

// ---------------- device scratch ----------------
__device__ int d_offsets[E + 1];
__device__ int d_cursor[E];
__device__ int d_blk[NHB * E];
__device__ int d_perm[BMAX];
__device__ int d_tick;
__device__ volatile int d_flag;
__device__ __align__(16) __half d_w1t[E * H * D];   // [e][n(H)][k(D)] fp16
__device__ __align__(16) __half d_w2t[E * D * H];   // [e][n(D)][k(H)] fp16

// ---------------- helpers ----------------
__device__ __forceinline__ uint32_t smem_u32(const void* p) {
    uint32_t a;
    asm("{ .reg .u64 t; cvta.to.shared.u64 t, %1; cvt.u32.u64 %0, t; }" : "=r"(a) : "l"(p));
    return a;
}
__device__ __forceinline__ uint32_t pack2(float a, float b) {
    __half2 h = __floats2half2_rn(a, b);
    return *(uint32_t*)&h;
}
__device__ __forceinline__ void cpa16(uint32_t dst, const void* src) {
    asm volatile("cp.async.cg.shared.global [%0], [%1], 16;" :: "r"(dst), "l"(src));
}
#define CP_COMMIT() asm volatile("cp.async.commit_group;" ::: "memory")
#define CP_WAIT0()  asm volatile("cp.async.wait_group 0;" ::: "memory")
#define LDM4(r0, r1, r2, r3, addr) \
    asm volatile("ldmatrix.sync.aligned.m8n8.x4.shared.b16 {%0,%1,%2,%3}, [%4];" \
        : "=r"(r0), "=r"(r1), "=r"(r2), "=r"(r3) : "r"(addr))

__device__ __forceinline__ void mma_f16(float* c, uint32_t a0, uint32_t a1, uint32_t a2,
                                        uint32_t a3, uint32_t b0, uint32_t b1) {
    asm volatile(
        "mma.sync.aligned.m16n8k16.row.col.f32.f16.f16.f32 "
        "{%0,%1,%2,%3}, {%4,%5,%6,%7}, {%8,%9}, {%0,%1,%2,%3};\n"
        : "+f"(c[0]), "+f"(c[1]), "+f"(c[2]), "+f"(c[3])
        : "r"(a0), "r"(a1), "r"(a2), "r"(a3), "r"(b0), "r"(b1));
}
__device__ __forceinline__ int load_id(const void* ids, int i, int is64) {
    return is64 ? (int)((const long long*)ids)[i] : ((const int*)ids)[i];
}

// ---------------- launch 1: fused hist + scan + scatter + weight transpose ----------------
__global__ void __launch_bounds__(256) k_prep(const void* __restrict__ ids, int B,
                                              const float* __restrict__ W1,
                                              const float* __restrict__ W2) {
    const int blk = blockIdx.x;
    const int t = threadIdx.x;
    if (blk < NHB) {
        __shared__ int sc[E];
        __shared__ int sbad;
        __shared__ int ticket;
        if (t < E) sc[t] = 0;
        if (t == 0) sbad = 0;
        __syncthreads();
        {   // dtype probe
            const long long* p = (const long long*)ids;
            int n = min(B / 2, 256);
            if (t < n) { long long v = p[t]; if (v < 0 || v >= E) sbad = 1; }
        }
        __syncthreads();
        const int is64 = !sbad;
        for (int i = blk * 256 + t; i < B; i += NHB * 256) {
            int e = load_id(ids, i, is64);
            if ((unsigned)e < E) atomicAdd(&sc[e], 1);
        }
        __syncthreads();
        if (t < E) d_blk[blk * E + t] = sc[t];
        __threadfence();
        if (t == 0) ticket = atomicAdd(&d_tick, 1);
        __syncthreads();
        if (ticket == NHB - 1 && t == 0) {
            int a = 0;
            for (int e = 0; e < E; e++) {
                int s = 0;
                for (int b = 0; b < NHB; b++) s += d_blk[b * E + e];
                d_offsets[e] = a; d_cursor[e] = a; a += s;
            }
            d_offsets[E] = a;
            d_tick = 0;
            __threadfence();
            d_flag = 1;
        }
        if (t == 0) { while (d_flag == 0) {} }
        __syncthreads();
        __threadfence();
        for (int i = blk * 256 + t; i < B; i += NHB * 256) {
            int e = load_id(ids, i, is64);
            if ((unsigned)e < E) {
                int p = atomicAdd(&d_cursor[e], 1);
                d_perm[p] = i;
            }
        }
    } else {
        __shared__ float ts[32][33];
        const int tx = t & 31, ty = t >> 5;
        const int tile = blk - NHB;
        const float* src;
        __half* dst;
        int k0, n0, srcLD, dstLD;
        if (tile < 336) {           // W1 [D][H] -> w1t [H][D]
            int e = tile / 48, r = tile % 48;
            k0 = (r >> 1) * 32; n0 = (r & 1) * 32;
            src = W1 + (size_t)e * D * H;  srcLD = H;
            dst = d_w1t + (size_t)e * H * D; dstLD = D;
        } else {                    // W2 [H][D] -> w2t [D][H]
            int t2 = tile - 336;
            int e = t2 / 48, r = t2 % 48;
            k0 = (r / 24) * 32; n0 = (r % 24) * 32;
            src = W2 + (size_t)e * H * D;  srcLD = D;
            dst = d_w2t + (size_t)e * D * H; dstLD = H;
        }
#pragma unroll
        for (int p = 0; p < 4; p++)
            ts[ty + 8 * p][tx] = src[(size_t)(k0 + ty + 8 * p) * srcLD + n0 + tx];
        __syncthreads();
#pragma unroll
        for (int p = 0; p < 4; p++)
            dst[(size_t)(n0 + ty + 8 * p) * dstLD + k0 + tx] =
                __float2half(ts[tx][ty + 8 * p]);
    }
}

// ---------------- smem layout (bytes) ----------------
// W1res  @ 0      : 64 * 1552  = 99328
// W2res  @ 99328  : 768 * 144  = 110592  (ends 209920)
// b1s    @ 209920 : 256
// b2s    @ 210176 : 3072
#define ROWB 144
#define W1LD 1552
#define OFF_W1 0
#define OFF_W2 99328
#define OFF_B1 209920
#define OFF_B2 210176
#define SMEM_BYTES 213248

// ---- x A-fragment helpers (direct gmem, quad-coalesced float2) ----
__device__ __forceinline__ void ldx_frag(float2 f[16], const float* xlo,
                                         const float* xhi, int kc, int tig) {
#pragma unroll
    for (int ks = 0; ks < 4; ks++) {
        const float* plo = xlo + kc + ks * 16 + 2 * tig;
        const float* phi = xhi + kc + ks * 16 + 2 * tig;
        f[4 * ks + 0] = __ldg((const float2*)plo);
        f[4 * ks + 1] = __ldg((const float2*)phi);
        f[4 * ks + 2] = __ldg((const float2*)(plo + 8));
        f[4 * ks + 3] = __ldg((const float2*)(phi + 8));
    }
}
__device__ __forceinline__ void cvt_frag(uint32_t xa[16], const float2 f[16]) {
#pragma unroll
    for (int q = 0; q < 16; q++) xa[q] = pack2(f[q].x, f[q].y);
}
__device__ __forceinline__ void g1_chunk_r(float acc[8][4], const uint32_t xa[16],
                                           uint32_t wbase) {
#pragma unroll
    for (int ks = 0; ks < 4; ks++) {
#pragma unroll
        for (int jt = 0; jt < 4; jt++) {
            uint32_t r0, r1, r2, r3;
            LDM4(r0, r1, r2, r3, wbase + jt * 16 * W1LD + ks * 32);
            mma_f16(acc[2 * jt],     xa[4 * ks], xa[4 * ks + 1], xa[4 * ks + 2], xa[4 * ks + 3], r0, r1);
            mma_f16(acc[2 * jt + 1], xa[4 * ks], xa[4 * ks + 1], xa[4 * ks + 2], xa[4 * ks + 3], r2, r3);
        }
    }
}

// ---------------- launch 2: barrier-free persistent kernel ----------------
// 16 warps, M-split only: warp w owns rows w*16+g, +8 of a 256-row tile.
// W1 + W2 fully smem-resident; X fragments from gmem; h in registers.
__global__ void __launch_bounds__(512)
k_main(const float* __restrict__ x, const float* __restrict__ b1,
       const float* __restrict__ b2, float* __restrict__ out)
{
    if (blockIdx.x == 0 && blockIdx.y == 0 && threadIdx.x == 0) d_flag = 0;

    const int e = blockIdx.y, cta = blockIdx.x;
    const int seg0 = d_offsets[e], seg1 = d_offsets[e + 1];
    const int ntiles = (seg1 - seg0 + 255) >> 8;

    extern __shared__ char smc[];
    const uint32_t sb = smem_u32(smc);
    float* b1s = (float*)(smc + OFF_B1);
    float* b2s = (float*)(smc + OFF_B2);

    const int tid = threadIdx.x, w = tid >> 5, lane = tid & 31;
    const int g = lane >> 2, tig = lane & 3;

    // ---- resident W1 (64 n-rows x 1536B) ----
    {
        const __half* W1e = d_w1t + (size_t)e * H * D;
        const int r = tid >> 3, sg = tid & 7;
        const uint32_t dst = sb + OFF_W1 + r * W1LD + sg * 192;
        const __half* src = W1e + r * D + sg * 96;
#pragma unroll
        for (int q = 0; q < 12; q++) cpa16(dst + q * 16, src + q * 8);
    }
    // ---- resident W2 (768 n-rows x 128B) ----
    {
        const __half* W2e = d_w2t + (size_t)e * D * H;
        for (int rr = tid; rr < D; rr += 512) {
            const uint32_t dst = sb + OFF_W2 + rr * ROWB;
            const __half* src = W2e + rr * H;
#pragma unroll
            for (int q = 0; q < 8; q++) cpa16(dst + q * 16, src + q * 8);
        }
    }
    CP_COMMIT();
    if (tid < H) b1s[tid] = b1[e * H + tid];
    for (int i = tid; i < D; i += 512) b2s[i] = b2[e * D + i];
    CP_WAIT0();
    __syncthreads();   // the ONLY barrier; tile loop below is barrier-free

    // fragment address cores (lane-dependent rows; jt/ks offsets added per use)
    const uint32_t w1_frag = sb + OFF_W1
        + ((lane & 7) + ((lane >> 4) & 1) * 8) * W1LD + ((lane >> 3) & 1) * 16;
    const uint32_t w2_frag = sb + OFF_W2
        + ((lane & 7) + ((lane >> 4) & 1) * 8) * ROWB + ((lane >> 3) & 1) * 16;

#pragma unroll 1
    for (int tile = cta; tile < ntiles; tile += CPE) {
        const int row0 = seg0 + tile * 256;
        const int nrows = seg1 - row0;               // may exceed 256; clamp below
        const int rlo = w * 16 + g, rhi = rlo + 8;
        const bool vlo = rlo < nrows, vhi = rhi < nrows;
        const int plo = d_perm[row0 + (vlo ? rlo : 0)];
        const int phi = d_perm[row0 + (vhi ? rhi : 0)];
        const float* xlo = x + (size_t)plo * D;
        const float* xhi = x + (size_t)phi * D;
        float* olo = out + (size_t)plo * D;
        float* ohi = out + (size_t)phi * D;

        // ============ GEMM1: h = relu(X @ W1^T + b1), dist-1 reg prefetch ============
        float acc[8][4];
#pragma unroll
        for (int nt = 0; nt < 8; nt++)
#pragma unroll
            for (int q = 0; q < 4; q++) acc[nt][q] = 0.f;

        float2 fE[16], fO[16];
        uint32_t xa[16];
        ldx_frag(fE, xlo, xhi, 0, tig);
#pragma unroll 1
        for (int ii = 0; ii < 6; ii++) {
            const int i0 = 2 * ii, i1 = i0 + 1;
            cvt_frag(xa, fE);
            ldx_frag(fO, xlo, xhi, i1 * 64, tig);          // i1 <= 11 always
            g1_chunk_r(acc, xa, w1_frag + i0 * 128);
            cvt_frag(xa, fO);
            if (i1 + 1 < 12) ldx_frag(fE, xlo, xhi, (i1 + 1) * 64, tig);
            g1_chunk_r(acc, xa, w1_frag + i1 * 128);
        }

        // ---- register transform: D-frags -> GEMM2 A-frags (bias+relu+fp16) ----
        uint32_t ha[4][4];
#pragma unroll
        for (int ks = 0; ks < 4; ks++) {
            const int c0 = (2 * ks) * 8 + 2 * tig;
            const int c1 = c0 + 8;
            float f0 = acc[2 * ks][0] + b1s[c0];
            float f1 = acc[2 * ks][1] + b1s[c0 + 1];
            float f2 = acc[2 * ks][2] + b1s[c0];
            float f3 = acc[2 * ks][3] + b1s[c0 + 1];
            float f4 = acc[2 * ks + 1][0] + b1s[c1];
            float f5 = acc[2 * ks + 1][1] + b1s[c1 + 1];
            float f6 = acc[2 * ks + 1][2] + b1s[c1];
            float f7 = acc[2 * ks + 1][3] + b1s[c1 + 1];
            ha[ks][0] = pack2(f0 > 0.f ? f0 : 0.f, f1 > 0.f ? f1 : 0.f);
            ha[ks][1] = pack2(f2 > 0.f ? f2 : 0.f, f3 > 0.f ? f3 : 0.f);
            ha[ks][2] = pack2(f4 > 0.f ? f4 : 0.f, f5 > 0.f ? f5 : 0.f);
            ha[ks][3] = pack2(f6 > 0.f ? f6 : 0.f, f7 > 0.f ? f7 : 0.f);
        }

        // ============ GEMM2: out = x + h @ W2^T + b2 (x from L2) ============
#pragma unroll 1
        for (int j = 0; j < 12; j++) {
            // epilogue-x prefetch (L2-hot; clamped rows -> always safe)
            float2 xel[8], xeh[8];
#pragma unroll
            for (int nt = 0; nt < 8; nt++) {
                const int cl = j * 64 + nt * 8 + 2 * tig;
                xel[nt] = *(const float2*)(xlo + cl);
                xeh[nt] = *(const float2*)(xhi + cl);
            }
            float acc2[8][4];
#pragma unroll
            for (int nt = 0; nt < 8; nt++)
#pragma unroll
                for (int q = 0; q < 4; q++) acc2[nt][q] = 0.f;

            const uint32_t wB = w2_frag + (j * 64) * ROWB;
#pragma unroll
            for (int ks = 0; ks < 4; ks++) {
#pragma unroll
                for (int jt = 0; jt < 4; jt++) {
                    uint32_t r0, r1, r2, r3;
                    LDM4(r0, r1, r2, r3, wB + jt * 16 * ROWB + ks * 32);
                    mma_f16(acc2[2 * jt],     ha[ks][0], ha[ks][1], ha[ks][2], ha[ks][3], r0, r1);
                    mma_f16(acc2[2 * jt + 1], ha[ks][0], ha[ks][1], ha[ks][2], ha[ks][3], r2, r3);
                }
            }
#pragma unroll
            for (int nt = 0; nt < 8; nt++) {
                const int cl = j * 64 + nt * 8 + 2 * tig;
                float2 bv = *(const float2*)(b2s + cl);
                if (vlo) {
                    float2 o = make_float2(xel[nt].x + acc2[nt][0] + bv.x,
                                           xel[nt].y + acc2[nt][1] + bv.y);
                    *(float2*)(olo + cl) = o;
                }
                if (vhi) {
                    float2 o = make_float2(xeh[nt].x + acc2[nt][2] + bv.x,
                                           xeh[nt].y + acc2[nt][3] + bv.y);
                    *(float2*)(ohi + cl) = o;
                }
            }
        }
    }
}

extern "C" void kernel_launch(void* const* d_in, const int* in_sizes, int n_in,
                              void* d_out, int out_size)
{
    const float* x   = (const float*)d_in[0];
    const void*  ids = d_in[1];
    const float* W1  = (const float*)d_in[2];
    const float* b1  = (const float*)d_in[3];
    const float* W2  = (const float*)d_in[4];
    const float* b2  = (const float*)d_in[5];
    float*       out = (float*)d_out;

    const int B = in_sizes[1];

    k_prep<<<NHB + 672, 256>>>(ids, B, W1, W2);

    cudaFuncSetAttribute(k_main, cudaFuncAttributeMaxDynamicSharedMemorySize, SMEM_BYTES);
    dim3 grid(CPE, E);
    k_main<<<grid, 512, SMEM_BYTES>>>(x, b1, b2, out);
}